// round 6
// baseline (speedup 1.0000x reference)
#include <cuda_runtime.h>

// SigKerMMD: 3 gram blocks (XX, XY, YY) of 64x64 pairs, each pair:
//   32x32 RBF gram -> 31x31 second difference -> 62x62 Goursat PDE -> corner value.
// out = (sum_XX - 2*sum_XY + sum_YY) / 4096
//
// Issue-bound kernel. FOUR pairs per warp; each pair handled by an 8-lane
// wavefront group, thread t owning PDE columns 8t+1..8t+8 (8 cells/step,
// 69 steps, ONE width-8 shuffle/step). Dyadic increments in FP32 (fp16 failed:
// MMD is a difference of nearly-cancelling means, absolute K errors don't cancel).
// 2 warps/block -> 38KB static smem (under the 48KB limit), ~5 blocks/SM.

#define WARPS_PER_BLOCK 2
#define THREADS_PER_BLOCK (WARPS_PER_BLOCK * 32)
#define NPAIRS 12288                       // 3 * 64 * 64
#define PAIRS_PER_WARP 4
#define NWARPS (NPAIRS / PAIRS_PER_WARP)   // 3072
#define NBLOCKS (NWARPS / WARPS_PER_BLOCK) // 1536
#define SEQ 32
#define CH 5
#define SEQCH (SEQ * CH)                   // 160

__device__ float g_block[NBLOCKS];
__device__ unsigned int g_done = 0;

__global__ __launch_bounds__(THREADS_PER_BLOCK)
void sig_pde_kernel(const float* __restrict__ x,
                    const float* __restrict__ y,
                    const float* __restrict__ sig,
                    float* __restrict__ out)
{
    __shared__ float sh_xa[WARPS_PER_BLOCK][PAIRS_PER_WARP][SEQCH];
    __shared__ float sh_xn[WARPS_PER_BLOCK][PAIRS_PER_WARP][SEQ];
    __shared__ float sh_aa[WARPS_PER_BLOCK][PAIRS_PER_WARP][31 * 32];
    __shared__ float sh_res[WARPS_PER_BLOCK][PAIRS_PER_WARP];
    __shared__ int   sh_last;
    __shared__ float sh_red[THREADS_PER_BLOCK];

    const int warp = threadIdx.x >> 5;
    const int lane = threadIdx.x & 31;
    const int wg   = blockIdx.x * WARPS_PER_BLOCK + warp;  // warp id 0..3071

    // channel scales for mu = [x0, x1*s0, x2*s1, x3*s2, x4*s3]
    float cs[CH];
    cs[0] = 1.0f;
    cs[1] = sig[0]; cs[2] = sig[1]; cs[3] = sig[2]; cs[4] = sig[3];

    // ======== Gram + dyadic increments for all 4 pairs (full warp each) ========
    #pragma unroll 1
    for (int g = 0; g < PAIRS_PER_WARP; g++) {
        const int w   = wg * PAIRS_PER_WARP + g;  // pair id 0..12287
        const int seg = w >> 12;                  // 0=XX, 1=XY, 2=YY
        const int p   = w & 4095;
        const int a   = p >> 6;
        const int b   = p & 63;

        const float* Aptr = ((seg < 2) ? x : y) + a * SEQCH;
        const bool   Ascale = (seg < 2);
        const float* Bptr = ((seg == 0) ? x : y) + b * SEQCH;
        const bool   Bscale = (seg == 0);

        // load A sequence (possibly sigma-scaled) into shared
        #pragma unroll
        for (int idx = lane; idx < SEQCH; idx += 32) {
            float v = Aptr[idx];
            if (Ascale) v *= cs[idx % CH];
            sh_xa[warp][g][idx] = v;
        }
        __syncwarp();

        // per-row squared norms of A
        {
            float s = 0.0f;
            #pragma unroll
            for (int c = 0; c < CH; c++) {
                float v = sh_xa[warp][g][lane * CH + c];
                s += v * v;
            }
            sh_xn[warp][g][lane] = s;
        }

        // B column (lane n) into registers
        float yb[CH];
        float yn = 0.0f;
        #pragma unroll
        for (int c = 0; c < CH; c++) {
            float v = Bptr[lane * CH + c];
            if (Bscale) v *= cs[c];
            yb[c] = v;
            yn += v * v;
        }
        __syncwarp();

        // gram column + second differences -> aa (fp32) in shared
        // colDiff[m-1][n] = G[m][n]-G[m-1][n]; aa = (colDiff[i][j+1]-colDiff[i][j])/4
        float gprev = 0.0f;
        #pragma unroll 4
        for (int m = 0; m < SEQ; m++) {
            float dot = 0.0f;
            #pragma unroll
            for (int c = 0; c < CH; c++)
                dot = fmaf(sh_xa[warp][g][m * CH + c], yb[c], dot);
            float d2 = sh_xn[warp][g][m] + yn - 2.0f * dot;
            float gv = __expf(-d2);         // RBF_SIGMA = 1.0
            if (m > 0) {
                float cd  = gv - gprev;
                float cdn = __shfl_down_sync(0xffffffffu, cd, 1);
                // lane 31 pads colpair 31 with zero (cols 63/64 are dummies)
                float aa = (lane < 31) ? (cdn - cd) * 0.25f : 0.0f;
                sh_aa[warp][g][(m - 1) * 32 + lane] = aa;
            }
            gprev = gv;
        }
        __syncwarp();
    }

    // ======== wavefront PDE: 8-lane group per pair, 8 cols per thread ========
    // K is (63x63) per pair, K[0][*]=K[*][0]=1.
    // K[i][j] = (K[i][j-1]+K[i-1][j])*c1 - K[i-1][j-1]*c2
    //   c1 = 1 + aa/2 + aa^2/12,  c2 = 1 - aa^2/12,  aa shared per 2x2 cell block.
    // thread t owns cols 8t+1..8t+8; step s computes row i = s - t + 1.
    // inD (= K[i-1][8t]) equals previous step's inL -> ONE shuffle per step.
    const int grp = lane >> 3;       // which pair in this warp (0..3)
    const int t   = lane & 7;        // wavefront thread index (0..7)

    float k1 = 1.0f, k2 = 1.0f, k3 = 1.0f, k4 = 1.0f;
    float k5 = 1.0f, k6 = 1.0f, k7 = 1.0f, k8 = 1.0f;
    float inD = 1.0f;
    float c1a = 1.0f, c2a = 1.0f, c1b = 1.0f, c2b = 1.0f;
    float c1c = 1.0f, c2c = 1.0f, c1d = 1.0f, c2d = 1.0f;
    const float4* ap = reinterpret_cast<const float4*>(&sh_aa[warp][grp][0]) + t;

    #pragma unroll 2
    for (int s = 0; s < 69; s++) {
        float inL = __shfl_up_sync(0xffffffffu, k8, 1, 8); // K[i][8t] from t-1
        if (t == 0) inL = 1.0f;                            // left boundary
        unsigned r = (unsigned)(s - t);                    // i-1
        if (r < 62u) {
            if (!(r & 1u)) {                               // new row-pair coeffs
                float4 v = *ap; ap += 8;                   // 8 float4 per row-pair
                float q;
                q = v.x * v.x * (1.0f / 12.0f);
                c1a = 1.0f + 0.5f * v.x + q;  c2a = 1.0f - q;
                q = v.y * v.y * (1.0f / 12.0f);
                c1b = 1.0f + 0.5f * v.y + q;  c2b = 1.0f - q;
                q = v.z * v.z * (1.0f / 12.0f);
                c1c = 1.0f + 0.5f * v.z + q;  c2c = 1.0f - q;
                q = v.w * v.w * (1.0f / 12.0f);
                c1d = 1.0f + 0.5f * v.w + q;  c2d = 1.0f - q;
            }
            float n1 = (inL + k1) * c1a - inD * c2a;
            float n2 = (n1  + k2) * c1a - k1  * c2a;
            float n3 = (n2  + k3) * c1b - k2  * c2b;
            float n4 = (n3  + k4) * c1b - k3  * c2b;
            float n5 = (n4  + k5) * c1c - k4  * c2c;
            float n6 = (n5  + k6) * c1c - k5  * c2c;
            float n7 = (n6  + k7) * c1d - k6  * c2d;
            float n8 = (n7  + k8) * c1d - k7  * c2d;
            k1 = n1; k2 = n2; k3 = n3; k4 = n4;
            k5 = n5; k6 = n6; k7 = n7; k8 = n8;
        }
        inD = inL;
    }

    // thread t=7 owns cols 57..64 -> k6 = K[62][62]
    if (t == 7) {
        const int seg = (wg * PAIRS_PER_WARP + grp) >> 12;
        float wgt = (seg == 1) ? -2.0f : 1.0f;
        sh_res[warp][grp] = wgt * k6;
    }
    __syncthreads();

    // ======== publish block partial + last-block fixed-order reduction ========
    if (threadIdx.x == 0) {
        float bsum = 0.0f;
        #pragma unroll
        for (int ww = 0; ww < WARPS_PER_BLOCK; ww++)
            bsum += (sh_res[ww][0] + sh_res[ww][1]) + (sh_res[ww][2] + sh_res[ww][3]);
        g_block[blockIdx.x] = bsum;
        __threadfence();
        unsigned tt = atomicAdd(&g_done, 1u);
        sh_last = (tt == NBLOCKS - 1);
    }
    __syncthreads();

    if (sh_last) {
        float s = 0.0f;
        #pragma unroll
        for (int i = threadIdx.x; i < NBLOCKS; i += THREADS_PER_BLOCK)
            s += g_block[i];
        sh_red[threadIdx.x] = s;
        __syncthreads();
        #pragma unroll
        for (int off = THREADS_PER_BLOCK / 2; off > 0; off >>= 1) {
            if (threadIdx.x < off) sh_red[threadIdx.x] += sh_red[threadIdx.x + off];
            __syncthreads();
        }
        if (threadIdx.x == 0) {
            out[0] = sh_red[0] * (1.0f / 4096.0f);
            g_done = 0;   // reset for next graph replay
        }
    }
}

extern "C" void kernel_launch(void* const* d_in, const int* in_sizes, int n_in,
                              void* d_out, int out_size)
{
    // Expected order: x [64*32*5], y [64*32*5], sigma_param [4].
    // Pick sigma defensively by element count.
    const float* x = nullptr;
    const float* yy = nullptr;
    const float* sp = nullptr;
    for (int i = 0; i < n_in; i++) {
        if (in_sizes[i] == CH - 1) { sp = (const float*)d_in[i]; }
        else if (!x)               { x  = (const float*)d_in[i]; }
        else if (!yy)              { yy = (const float*)d_in[i]; }
    }

    sig_pde_kernel<<<NBLOCKS, THREADS_PER_BLOCK>>>(x, yy, sp, (float*)d_out);
}

// round 8
// speedup vs baseline: 1.5436x; 1.5436x over previous
#include <cuda_runtime.h>

// SigKerMMD, two-phase: (1) gram+dyadic increments -> global staging (L2-resident),
// (2) wavefront Goursat PDE with register ring prefetch + fused deterministic reduce.
// out = (sum_XX - 2*sum_XY + sum_YY) / 4096
//
// R6 lesson: fused kernel needs ~4.7KB smem per in-flight pair -> occupancy hard
// cap ~12 warps/SM. Staging aa in global (L2-resident, DRAM idle) frees smem so
// the PDE phase runs a full wave at ~20 warps/SM.

#define SEQ 32
#define CH 5
#define SEQCH (SEQ * CH)          // 160
#define NPAIRS 12288              // 3 * 64 * 64

#define AA_RP 34                  // 31 used row-pairs + 3 ring preloads
#define AA_STRIDE (AA_RP * 32)    // floats per pair

#define G1_WARPS 8
#define G1_BLOCKS (NPAIRS / G1_WARPS)        // 1536

#define P2_WARPS 4
#define PAIRS_PER_WARP 4
#define NWARPS2 (NPAIRS / PAIRS_PER_WARP)    // 3072
#define P2_BLOCKS (NWARPS2 / P2_WARPS)       // 768

__device__ float g_aa[(size_t)NPAIRS * AA_STRIDE];   // ~53.5 MB staging
__device__ float g_block[P2_BLOCKS];
__device__ unsigned int g_done = 0;

// ===================== Phase 1: gram + dyadic increments =====================
__global__ __launch_bounds__(G1_WARPS * 32)
void gram_kernel(const float* __restrict__ x,
                 const float* __restrict__ y,
                 const float* __restrict__ sig)
{
    __shared__ float sh_xa[G1_WARPS][SEQCH];
    __shared__ float sh_xn[G1_WARPS][SEQ];

    const int warp = threadIdx.x >> 5;
    const int lane = threadIdx.x & 31;
    const int w = blockIdx.x * G1_WARPS + warp;   // pair id 0..12287

    const int seg = w >> 12;          // 0=XX, 1=XY, 2=YY
    const int p   = w & 4095;
    const int a   = p >> 6;
    const int b   = p & 63;

    // channel scales for mu = [x0, x1*s0, x2*s1, x3*s2, x4*s3]
    float cs[CH];
    cs[0] = 1.0f;
    cs[1] = sig[0]; cs[2] = sig[1]; cs[3] = sig[2]; cs[4] = sig[3];

    const float* Aptr = ((seg < 2) ? x : y) + a * SEQCH;
    const bool   Ascale = (seg < 2);
    const float* Bptr = ((seg == 0) ? x : y) + b * SEQCH;
    const bool   Bscale = (seg == 0);

    // load A sequence (possibly sigma-scaled) into shared
    #pragma unroll
    for (int idx = lane; idx < SEQCH; idx += 32) {
        float v = Aptr[idx];
        if (Ascale) v *= cs[idx % CH];
        sh_xa[warp][idx] = v;
    }
    __syncwarp();

    // per-row squared norms of A
    {
        float s = 0.0f;
        #pragma unroll
        for (int c = 0; c < CH; c++) {
            float v = sh_xa[warp][lane * CH + c];
            s += v * v;
        }
        sh_xn[warp][lane] = s;
    }

    // B column (lane n) into registers
    float yb[CH];
    float yn = 0.0f;
    #pragma unroll
    for (int c = 0; c < CH; c++) {
        float v = Bptr[lane * CH + c];
        if (Bscale) v *= cs[c];
        yb[c] = v;
        yn += v * v;
    }
    __syncwarp();

    // gram column + second differences -> aa (fp32) in global staging
    // colDiff[m-1][n] = G[m][n]-G[m-1][n]; aa = (colDiff[i][j+1]-colDiff[i][j])/4
    float* aout = g_aa + (size_t)w * AA_STRIDE + lane;
    float gprev = 0.0f;
    #pragma unroll 4
    for (int m = 0; m < SEQ; m++) {
        float dot = 0.0f;
        #pragma unroll
        for (int c = 0; c < CH; c++)
            dot = fmaf(sh_xa[warp][m * CH + c], yb[c], dot);
        float d2 = sh_xn[warp][m] + yn - 2.0f * dot;
        float gv = __expf(-d2);         // RBF_SIGMA = 1.0
        if (m > 0) {
            float cd  = gv - gprev;
            float cdn = __shfl_down_sync(0xffffffffu, cd, 1);
            // lane 31 pads colpair 31 with zero (cols 63/64 are dummies)
            float aa = (lane < 31) ? (cdn - cd) * 0.25f : 0.0f;
            aout[(m - 1) * 32] = aa;
        }
        gprev = gv;
    }
}

// ===================== Phase 2: wavefront PDE + reduction =====================
// K is (63x63) per pair, K[0][*]=K[*][0]=1.
// K[i][j] = (K[i][j-1]+K[i-1][j])*c1 - K[i-1][j-1]*c2
//   c1 = 1 + aa/2 + aa^2/12,  c2 = 1 - aa^2/12,  aa shared per 2x2 cell block.
// 8-lane group per pair; thread t owns cols 8t+1..8t+8; step s computes row
// i = s - t + 1; ONE width-8 shuffle per step (inD = previous step's inL).
// aa streamed from global through a 3-deep register ring (prefetch ~6 steps).
__global__ __launch_bounds__(P2_WARPS * 32)
void pde_kernel(float* __restrict__ out)
{
    __shared__ float sh_res[P2_WARPS][PAIRS_PER_WARP];
    __shared__ int   sh_last;
    __shared__ float sh_red[P2_WARPS * 32];

    const int warp = threadIdx.x >> 5;
    const int lane = threadIdx.x & 31;
    const int wg   = blockIdx.x * P2_WARPS + warp;   // warp id 0..3071
    const int grp  = lane >> 3;                      // pair within warp (0..3)
    const int t    = lane & 7;                       // wavefront thread (0..7)
    const int pair = wg * PAIRS_PER_WARP + grp;      // pair id 0..12287

    const float4* ap = reinterpret_cast<const float4*>(
                           g_aa + (size_t)pair * AA_STRIDE) + t;

    // prefetch ring: cur = next row-pair to consume
    float4 cur = ap[0];
    float4 nxt = ap[8];
    float4 nx2 = ap[16];
    ap += 24;
    int remaining = 31 - 3;   // row-pair loads left after preloads

    float k1 = 1.0f, k2 = 1.0f, k3 = 1.0f, k4 = 1.0f;
    float k5 = 1.0f, k6 = 1.0f, k7 = 1.0f, k8 = 1.0f;
    float inD = 1.0f;
    float c1a = 1.0f, c2a = 1.0f, c1b = 1.0f, c2b = 1.0f;
    float c1c = 1.0f, c2c = 1.0f, c1d = 1.0f, c2d = 1.0f;

    #pragma unroll 2
    for (int s = 0; s < 69; s++) {
        float inL = __shfl_up_sync(0xffffffffu, k8, 1, 8); // K[i][8t] from t-1
        if (t == 0) inL = 1.0f;                            // left boundary
        unsigned r = (unsigned)(s - t);                    // i-1
        if (r < 62u) {
            if (!(r & 1u)) {                               // new row-pair coeffs
                float q;
                q = cur.x * cur.x * (1.0f / 12.0f);
                c1a = 1.0f + 0.5f * cur.x + q;  c2a = 1.0f - q;
                q = cur.y * cur.y * (1.0f / 12.0f);
                c1b = 1.0f + 0.5f * cur.y + q;  c2b = 1.0f - q;
                q = cur.z * cur.z * (1.0f / 12.0f);
                c1c = 1.0f + 0.5f * cur.z + q;  c2c = 1.0f - q;
                q = cur.w * cur.w * (1.0f / 12.0f);
                c1d = 1.0f + 0.5f * cur.w + q;  c2d = 1.0f - q;
                cur = nxt; nxt = nx2;
                if (remaining > 0) {                        // stay in-bounds
                    nx2 = *ap; ap += 8; remaining--;
                }
            }
            float n1 = (inL + k1) * c1a - inD * c2a;
            float n2 = (n1  + k2) * c1a - k1  * c2a;
            float n3 = (n2  + k3) * c1b - k2  * c2b;
            float n4 = (n3  + k4) * c1b - k3  * c2b;
            float n5 = (n4  + k5) * c1c - k4  * c2c;
            float n6 = (n5  + k6) * c1c - k5  * c2c;
            float n7 = (n6  + k7) * c1d - k6  * c2d;
            float n8 = (n7  + k8) * c1d - k7  * c2d;
            k1 = n1; k2 = n2; k3 = n3; k4 = n4;
            k5 = n5; k6 = n6; k7 = n7; k8 = n8;
        }
        inD = inL;
    }

    // thread t=7 owns cols 57..64 -> k6 = K[62][62]
    if (t == 7) {
        const int seg = pair >> 12;
        float wgt = (seg == 1) ? -2.0f : 1.0f;
        sh_res[warp][grp] = wgt * k6;
    }
    __syncthreads();

    // publish block partial + last-block fixed-order reduction
    if (threadIdx.x == 0) {
        float bsum = 0.0f;
        #pragma unroll
        for (int ww = 0; ww < P2_WARPS; ww++)
            bsum += (sh_res[ww][0] + sh_res[ww][1]) + (sh_res[ww][2] + sh_res[ww][3]);
        g_block[blockIdx.x] = bsum;
        __threadfence();
        unsigned tt = atomicAdd(&g_done, 1u);
        sh_last = (tt == P2_BLOCKS - 1);
    }
    __syncthreads();

    if (sh_last) {
        float s = 0.0f;
        #pragma unroll 1
        for (int i = threadIdx.x; i < P2_BLOCKS; i += P2_WARPS * 32)
            s += g_block[i];
        sh_red[threadIdx.x] = s;
        __syncthreads();
        #pragma unroll
        for (int off = P2_WARPS * 16; off > 0; off >>= 1) {
            if (threadIdx.x < off) sh_red[threadIdx.x] += sh_red[threadIdx.x + off];
            __syncthreads();
        }
        if (threadIdx.x == 0) {
            out[0] = sh_red[0] * (1.0f / 4096.0f);
            g_done = 0;   // reset for next graph replay
        }
    }
}

extern "C" void kernel_launch(void* const* d_in, const int* in_sizes, int n_in,
                              void* d_out, int out_size)
{
    // Expected order: x [64*32*5], y [64*32*5], sigma_param [4].
    // Pick sigma defensively by element count.
    const float* x = nullptr;
    const float* yy = nullptr;
    const float* sp = nullptr;
    for (int i = 0; i < n_in; i++) {
        if (in_sizes[i] == CH - 1) { sp = (const float*)d_in[i]; }
        else if (!x)               { x  = (const float*)d_in[i]; }
        else if (!yy)              { yy = (const float*)d_in[i]; }
    }

    gram_kernel<<<G1_BLOCKS, G1_WARPS * 32>>>(x, yy, sp);
    pde_kernel<<<P2_BLOCKS, P2_WARPS * 32>>>((float*)d_out);
}

// round 9
// speedup vs baseline: 1.9818x; 1.2839x over previous
#include <cuda_runtime.h>

// SigKerMMD with triangle symmetry: K(a,b)=K(b,a) for XX and YY blocks
// (Goursat recurrence is transpose-symmetric), so work = 2080 + 4096 + 2080
// = 8256 pairs instead of 12288. Off-diagonal tri pairs weighted x2.
// out = (sum_XX - 2*sum_XY + sum_YY) / 4096
//
// Single fused kernel: each warp computes gram+increments for its 4 pairs,
// stages aa through global (written & read by the SAME warp -> L2-resident,
// no DRAM dependency; R8 split version streamed 49MB from DRAM), then runs
// the 8-lane-group wavefront PDE (8 cols/thread, 1 shuffle/step, register
// ring prefetch) and a fused deterministic last-block reduction.

#define SEQ 32
#define CH 5
#define SEQCH (SEQ * CH)          // 160
#define NTRI 2080                 // 64*65/2
#define NPAIRS (NTRI + 4096 + NTRI)          // 8256
#define PAIRS_PER_WARP 4
#define NWARPS (NPAIRS / PAIRS_PER_WARP)     // 2064
#define WARPS_PER_BLOCK 4
#define NBLOCKS (NWARPS / WARPS_PER_BLOCK)   // 516
#define THREADS_PER_BLOCK (WARPS_PER_BLOCK * 32)

#define AA_RP 31
#define AA_STRIDE (AA_RP * 32)    // 992 floats (3968B, float4-aligned) per pair

__device__ float g_aa[(size_t)NPAIRS * AA_STRIDE];   // ~32.8 MB staging
__device__ float g_block[NBLOCKS];
__device__ unsigned int g_done = 0;

// decode work item -> (seg, a, b, weight). Layout:
//   [0, 2080)      XX upper triangle (a<=b), weight 2 off-diag / 1 diag
//   [2080, 6176)   XY full, weight -2
//   [6176, 8256)   YY upper triangle, weight 2 off-diag / 1 diag
__device__ __forceinline__ void decode_pair(int w, int& seg, int& a, int& b, float& wgt)
{
    if (w < NTRI) {
        seg = 0;
        int t = w;
        int ar = (int)((129.0f - sqrtf(16641.0f - 8.0f * (float)t)) * 0.5f);
        if (ar < 0) ar = 0;
        // fixup fp rounding: offset(a) = 64a - a(a-1)/2
        while (ar > 0 && (ar * 64 - (ar * (ar - 1)) / 2) > t) ar--;
        while (((ar + 1) * 64 - ((ar + 1) * ar) / 2) <= t) ar++;
        a = ar;
        b = ar + (t - (ar * 64 - (ar * (ar - 1)) / 2));
        wgt = (a == b) ? 1.0f : 2.0f;
    } else if (w < NTRI + 4096) {
        seg = 1;
        int p = w - NTRI;
        a = p >> 6;
        b = p & 63;
        wgt = -2.0f;
    } else {
        seg = 2;
        int t = w - (NTRI + 4096);
        int ar = (int)((129.0f - sqrtf(16641.0f - 8.0f * (float)t)) * 0.5f);
        if (ar < 0) ar = 0;
        while (ar > 0 && (ar * 64 - (ar * (ar - 1)) / 2) > t) ar--;
        while (((ar + 1) * 64 - ((ar + 1) * ar) / 2) <= t) ar++;
        a = ar;
        b = ar + (t - (ar * 64 - (ar * (ar - 1)) / 2));
        wgt = (a == b) ? 1.0f : 2.0f;
    }
}

__global__ __launch_bounds__(THREADS_PER_BLOCK)
void sig_kernel(const float* __restrict__ x,
                const float* __restrict__ y,
                const float* __restrict__ sig,
                float* __restrict__ out)
{
    __shared__ float sh_xa[WARPS_PER_BLOCK][SEQCH];
    __shared__ float sh_xn[WARPS_PER_BLOCK][SEQ];
    __shared__ float sh_res[WARPS_PER_BLOCK][PAIRS_PER_WARP];
    __shared__ int   sh_last;
    __shared__ float sh_red[THREADS_PER_BLOCK];

    const int warp = threadIdx.x >> 5;
    const int lane = threadIdx.x & 31;
    const int wg   = blockIdx.x * WARPS_PER_BLOCK + warp;  // warp id 0..2063

    // channel scales for mu = [x0, x1*s0, x2*s1, x3*s2, x4*s3]
    float cs[CH];
    cs[0] = 1.0f;
    cs[1] = sig[0]; cs[2] = sig[1]; cs[3] = sig[2]; cs[4] = sig[3];

    // ======== Phase A: gram + dyadic increments for 4 pairs (full warp) ========
    #pragma unroll 1
    for (int g = 0; g < PAIRS_PER_WARP; g++) {
        const int w = wg * PAIRS_PER_WARP + g;    // work item 0..8255
        int seg, a, b; float wdummy;
        decode_pair(w, seg, a, b, wdummy);

        const float* Aptr = ((seg < 2) ? x : y) + a * SEQCH;
        const bool   Ascale = (seg < 2);
        const float* Bptr = ((seg == 0) ? x : y) + b * SEQCH;
        const bool   Bscale = (seg == 0);

        // load A sequence (possibly sigma-scaled) into shared
        #pragma unroll
        for (int idx = lane; idx < SEQCH; idx += 32) {
            float v = Aptr[idx];
            if (Ascale) v *= cs[idx % CH];
            sh_xa[warp][idx] = v;
        }
        __syncwarp();

        // per-row squared norms of A
        {
            float s = 0.0f;
            #pragma unroll
            for (int c = 0; c < CH; c++) {
                float v = sh_xa[warp][lane * CH + c];
                s += v * v;
            }
            sh_xn[warp][lane] = s;
        }

        // B column (lane n) into registers
        float yb[CH];
        float yn = 0.0f;
        #pragma unroll
        for (int c = 0; c < CH; c++) {
            float v = Bptr[lane * CH + c];
            if (Bscale) v *= cs[c];
            yb[c] = v;
            yn += v * v;
        }
        __syncwarp();

        // gram column + second differences -> aa (fp32) to global staging
        // colDiff[m-1][n] = G[m][n]-G[m-1][n]; aa = (colDiff[i][j+1]-colDiff[i][j])/4
        float* aout = g_aa + (size_t)w * AA_STRIDE + lane;
        float gprev = 0.0f;
        #pragma unroll 4
        for (int m = 0; m < SEQ; m++) {
            float dot = 0.0f;
            #pragma unroll
            for (int c = 0; c < CH; c++)
                dot = fmaf(sh_xa[warp][m * CH + c], yb[c], dot);
            float d2 = sh_xn[warp][m] + yn - 2.0f * dot;
            float gv = __expf(-d2);         // RBF_SIGMA = 1.0
            if (m > 0) {
                float cd  = gv - gprev;
                float cdn = __shfl_down_sync(0xffffffffu, cd, 1);
                // lane 31 pads colpair 31 with zero (cols 63/64 are dummies)
                float aa = (lane < 31) ? (cdn - cd) * 0.25f : 0.0f;
                aout[(m - 1) * 32] = aa;
            }
            gprev = gv;
        }
        __syncwarp();
    }

    // make this warp's aa stores visible to its own cross-lane reads
    __threadfence_block();
    __syncwarp();

    // ======== Phase B: wavefront PDE (8-lane group per pair) ========
    // K is (63x63) per pair, K[0][*]=K[*][0]=1.
    // K[i][j] = (K[i][j-1]+K[i-1][j])*c1 - K[i-1][j-1]*c2
    //   c1 = 1 + aa/2 + aa^2/12,  c2 = 1 - aa^2/12,  aa shared per 2x2 cell block.
    // thread t owns cols 8t+1..8t+8; step s computes row i = s - t + 1.
    // inD (= K[i-1][8t]) equals previous step's inL -> ONE shuffle per step.
    // aa streamed from L2 through a 3-deep register ring (~6 steps ahead).
    const int grp  = lane >> 3;                    // pair within warp (0..3)
    const int t    = lane & 7;                     // wavefront thread (0..7)
    const int pair = wg * PAIRS_PER_WARP + grp;    // work item of this group

    int segp, ap_, bp_; float wgt;
    decode_pair(pair, segp, ap_, bp_, wgt);

    const float4* ap = reinterpret_cast<const float4*>(
                           g_aa + (size_t)pair * AA_STRIDE) + t;

    // prefetch ring: cur = next row-pair to consume
    float4 cur = ap[0];
    float4 nxt = ap[8];
    float4 nx2 = ap[16];
    ap += 24;
    int remaining = 31 - 3;   // row-pair loads left after preloads

    float k1 = 1.0f, k2 = 1.0f, k3 = 1.0f, k4 = 1.0f;
    float k5 = 1.0f, k6 = 1.0f, k7 = 1.0f, k8 = 1.0f;
    float inD = 1.0f;
    float c1a = 1.0f, c2a = 1.0f, c1b = 1.0f, c2b = 1.0f;
    float c1c = 1.0f, c2c = 1.0f, c1d = 1.0f, c2d = 1.0f;

    #pragma unroll 2
    for (int s = 0; s < 69; s++) {
        float inL = __shfl_up_sync(0xffffffffu, k8, 1, 8); // K[i][8t] from t-1
        if (t == 0) inL = 1.0f;                            // left boundary
        unsigned r = (unsigned)(s - t);                    // i-1
        if (r < 62u) {
            if (!(r & 1u)) {                               // new row-pair coeffs
                float q;
                q = cur.x * cur.x * (1.0f / 12.0f);
                c1a = 1.0f + 0.5f * cur.x + q;  c2a = 1.0f - q;
                q = cur.y * cur.y * (1.0f / 12.0f);
                c1b = 1.0f + 0.5f * cur.y + q;  c2b = 1.0f - q;
                q = cur.z * cur.z * (1.0f / 12.0f);
                c1c = 1.0f + 0.5f * cur.z + q;  c2c = 1.0f - q;
                q = cur.w * cur.w * (1.0f / 12.0f);
                c1d = 1.0f + 0.5f * cur.w + q;  c2d = 1.0f - q;
                cur = nxt; nxt = nx2;
                if (remaining > 0) {                        // stay in-bounds
                    nx2 = *ap; ap += 8; remaining--;
                }
            }
            float n1 = (inL + k1) * c1a - inD * c2a;
            float n2 = (n1  + k2) * c1a - k1  * c2a;
            float n3 = (n2  + k3) * c1b - k2  * c2b;
            float n4 = (n3  + k4) * c1b - k3  * c2b;
            float n5 = (n4  + k5) * c1c - k4  * c2c;
            float n6 = (n5  + k6) * c1c - k5  * c2c;
            float n7 = (n6  + k7) * c1d - k6  * c2d;
            float n8 = (n7  + k8) * c1d - k7  * c2d;
            k1 = n1; k2 = n2; k3 = n3; k4 = n4;
            k5 = n5; k6 = n6; k7 = n7; k8 = n8;
        }
        inD = inL;
    }

    // thread t=7 owns cols 57..64 -> k6 = K[62][62]
    if (t == 7)
        sh_res[warp][grp] = wgt * k6;
    __syncthreads();

    // ======== publish block partial + last-block fixed-order reduction ========
    if (threadIdx.x == 0) {
        float bsum = 0.0f;
        #pragma unroll
        for (int ww = 0; ww < WARPS_PER_BLOCK; ww++)
            bsum += (sh_res[ww][0] + sh_res[ww][1]) + (sh_res[ww][2] + sh_res[ww][3]);
        g_block[blockIdx.x] = bsum;
        __threadfence();
        unsigned tt = atomicAdd(&g_done, 1u);
        sh_last = (tt == NBLOCKS - 1);
    }
    __syncthreads();

    if (sh_last) {
        float s = 0.0f;
        #pragma unroll 1
        for (int i = threadIdx.x; i < NBLOCKS; i += THREADS_PER_BLOCK)
            s += g_block[i];
        sh_red[threadIdx.x] = s;
        __syncthreads();
        #pragma unroll
        for (int off = THREADS_PER_BLOCK / 2; off > 0; off >>= 1) {
            if (threadIdx.x < off) sh_red[threadIdx.x] += sh_red[threadIdx.x + off];
            __syncthreads();
        }
        if (threadIdx.x == 0) {
            out[0] = sh_red[0] * (1.0f / 4096.0f);
            g_done = 0;   // reset for next graph replay
        }
    }
}

extern "C" void kernel_launch(void* const* d_in, const int* in_sizes, int n_in,
                              void* d_out, int out_size)
{
    // Expected order: x [64*32*5], y [64*32*5], sigma_param [4].
    // Pick sigma defensively by element count.
    const float* x = nullptr;
    const float* yy = nullptr;
    const float* sp = nullptr;
    for (int i = 0; i < n_in; i++) {
        if (in_sizes[i] == CH - 1) { sp = (const float*)d_in[i]; }
        else if (!x)               { x  = (const float*)d_in[i]; }
        else if (!yy)              { yy = (const float*)d_in[i]; }
    }

    sig_kernel<<<NBLOCKS, THREADS_PER_BLOCK>>>(x, yy, sp, (float*)d_out);
}

// round 10
// speedup vs baseline: 1.9963x; 1.0073x over previous
#include <cuda_runtime.h>

// SigKerMMD with triangle symmetry: K(a,b)=K(b,a) for XX and YY blocks
// (Goursat recurrence is transpose-symmetric), so work = 2080 + 4096 + 2080
// = 8256 pairs instead of 12288. Off-diagonal tri pairs weighted x2.
// out = (sum_XX - 2*sum_XY + sum_YY) / 4096
//
// Single fused kernel: each warp computes gram+increments for its 4 pairs,
// stages aa through global (written & read by the SAME warp -> L2-resident),
// then runs the 8-lane-group wavefront PDE. R10: linear-recurrence split
// n_j = c1_j*n_{j-1} + b_j with b_j precomputable in parallel -> per-step
// critical path drops 90 -> ~58 cyc; shuffle hoisted to loop bottom so its
// latency overlaps the next step's b computations.

#define SEQ 32
#define CH 5
#define SEQCH (SEQ * CH)          // 160
#define NTRI 2080                 // 64*65/2
#define NPAIRS (NTRI + 4096 + NTRI)          // 8256
#define PAIRS_PER_WARP 4
#define NWARPS (NPAIRS / PAIRS_PER_WARP)     // 2064
#define WARPS_PER_BLOCK 4
#define NBLOCKS (NWARPS / WARPS_PER_BLOCK)   // 516
#define THREADS_PER_BLOCK (WARPS_PER_BLOCK * 32)

#define AA_RP 31
#define AA_STRIDE (AA_RP * 32)    // 992 floats (3968B, float4-aligned) per pair

__device__ float g_aa[(size_t)NPAIRS * AA_STRIDE];   // ~32.8 MB staging
__device__ float g_block[NBLOCKS];
__device__ unsigned int g_done = 0;

// decode work item -> (seg, a, b, weight). Layout:
//   [0, 2080)      XX upper triangle (a<=b), weight 2 off-diag / 1 diag
//   [2080, 6176)   XY full, weight -2
//   [6176, 8256)   YY upper triangle, weight 2 off-diag / 1 diag
__device__ __forceinline__ void decode_pair(int w, int& seg, int& a, int& b, float& wgt)
{
    if (w < NTRI) {
        seg = 0;
        int t = w;
        int ar = (int)((129.0f - sqrtf(16641.0f - 8.0f * (float)t)) * 0.5f);
        if (ar < 0) ar = 0;
        // fixup fp rounding: offset(a) = 64a - a(a-1)/2
        while (ar > 0 && (ar * 64 - (ar * (ar - 1)) / 2) > t) ar--;
        while (((ar + 1) * 64 - ((ar + 1) * ar) / 2) <= t) ar++;
        a = ar;
        b = ar + (t - (ar * 64 - (ar * (ar - 1)) / 2));
        wgt = (a == b) ? 1.0f : 2.0f;
    } else if (w < NTRI + 4096) {
        seg = 1;
        int p = w - NTRI;
        a = p >> 6;
        b = p & 63;
        wgt = -2.0f;
    } else {
        seg = 2;
        int t = w - (NTRI + 4096);
        int ar = (int)((129.0f - sqrtf(16641.0f - 8.0f * (float)t)) * 0.5f);
        if (ar < 0) ar = 0;
        while (ar > 0 && (ar * 64 - (ar * (ar - 1)) / 2) > t) ar--;
        while (((ar + 1) * 64 - ((ar + 1) * ar) / 2) <= t) ar++;
        a = ar;
        b = ar + (t - (ar * 64 - (ar * (ar - 1)) / 2));
        wgt = (a == b) ? 1.0f : 2.0f;
    }
}

__global__ __launch_bounds__(THREADS_PER_BLOCK)
void sig_kernel(const float* __restrict__ x,
                const float* __restrict__ y,
                const float* __restrict__ sig,
                float* __restrict__ out)
{
    __shared__ float sh_xa[WARPS_PER_BLOCK][SEQCH];
    __shared__ float sh_xn[WARPS_PER_BLOCK][SEQ];
    __shared__ float sh_res[WARPS_PER_BLOCK][PAIRS_PER_WARP];
    __shared__ int   sh_last;
    __shared__ float sh_red[THREADS_PER_BLOCK];

    const int warp = threadIdx.x >> 5;
    const int lane = threadIdx.x & 31;
    const int wg   = blockIdx.x * WARPS_PER_BLOCK + warp;  // warp id 0..2063

    // channel scales for mu = [x0, x1*s0, x2*s1, x3*s2, x4*s3]
    float cs[CH];
    cs[0] = 1.0f;
    cs[1] = sig[0]; cs[2] = sig[1]; cs[3] = sig[2]; cs[4] = sig[3];

    // ======== Phase A: gram + dyadic increments for 4 pairs (full warp) ========
    #pragma unroll 1
    for (int g = 0; g < PAIRS_PER_WARP; g++) {
        const int w = wg * PAIRS_PER_WARP + g;    // work item 0..8255
        int seg, a, b; float wdummy;
        decode_pair(w, seg, a, b, wdummy);

        const float* Aptr = ((seg < 2) ? x : y) + a * SEQCH;
        const bool   Ascale = (seg < 2);
        const float* Bptr = ((seg == 0) ? x : y) + b * SEQCH;
        const bool   Bscale = (seg == 0);

        // load A sequence (possibly sigma-scaled) into shared
        #pragma unroll
        for (int idx = lane; idx < SEQCH; idx += 32) {
            float v = Aptr[idx];
            if (Ascale) v *= cs[idx % CH];
            sh_xa[warp][idx] = v;
        }
        __syncwarp();

        // per-row squared norms of A
        {
            float s = 0.0f;
            #pragma unroll
            for (int c = 0; c < CH; c++) {
                float v = sh_xa[warp][lane * CH + c];
                s += v * v;
            }
            sh_xn[warp][lane] = s;
        }

        // B column (lane n) into registers
        float yb[CH];
        float yn = 0.0f;
        #pragma unroll
        for (int c = 0; c < CH; c++) {
            float v = Bptr[lane * CH + c];
            if (Bscale) v *= cs[c];
            yb[c] = v;
            yn += v * v;
        }
        __syncwarp();

        // gram column + second differences -> aa (fp32) to global staging
        // colDiff[m-1][n] = G[m][n]-G[m-1][n]; aa = (colDiff[i][j+1]-colDiff[i][j])/4
        float* aout = g_aa + (size_t)w * AA_STRIDE + lane;
        float gprev = 0.0f;
        #pragma unroll 4
        for (int m = 0; m < SEQ; m++) {
            float dot = 0.0f;
            #pragma unroll
            for (int c = 0; c < CH; c++)
                dot = fmaf(sh_xa[warp][m * CH + c], yb[c], dot);
            float d2 = sh_xn[warp][m] + yn - 2.0f * dot;
            float gv = __expf(-d2);         // RBF_SIGMA = 1.0
            if (m > 0) {
                float cd  = gv - gprev;
                float cdn = __shfl_down_sync(0xffffffffu, cd, 1);
                // lane 31 pads colpair 31 with zero (cols 63/64 are dummies)
                float aa = (lane < 31) ? (cdn - cd) * 0.25f : 0.0f;
                aout[(m - 1) * 32] = aa;
            }
            gprev = gv;
        }
        __syncwarp();
    }

    // make this warp's aa stores visible to its own cross-lane reads
    __threadfence_block();
    __syncwarp();

    // ======== Phase B: wavefront PDE (8-lane group per pair) ========
    // K is (63x63) per pair, K[0][*]=K[*][0]=1.
    // K[i][j] = (K[i][j-1]+K[i-1][j])*c1 - K[i-1][j-1]*c2
    // Rewritten: n_j = c1_j * n_{j-1} + b_j,  b_j = c1_j*k_j - c2_j*k_{j-1}
    // (b_j depend only on previous-row state -> computed in parallel, overlap
    //  the shuffle; serial chain = 8 single FFMAs instead of 8 FADD+FFMA).
    // thread t owns cols 8t+1..8t+8; step s computes row i = s - t + 1.
    // inD (= K[i-1][8t]) equals previous step's inL; shuffle issued at loop
    // bottom so its latency overlaps the next step's b computations.
    const int grp  = lane >> 3;                    // pair within warp (0..3)
    const int t    = lane & 7;                     // wavefront thread (0..7)
    const int pair = wg * PAIRS_PER_WARP + grp;    // work item of this group

    int segp, ap_, bp_; float wgt;
    decode_pair(pair, segp, ap_, bp_, wgt);

    const float4* ap = reinterpret_cast<const float4*>(
                           g_aa + (size_t)pair * AA_STRIDE) + t;

    // prefetch ring: cur = next row-pair to consume
    float4 cur = ap[0];
    float4 nxt = ap[8];
    float4 nx2 = ap[16];
    ap += 24;
    int remaining = 31 - 3;   // row-pair loads left after preloads

    float k1 = 1.0f, k2 = 1.0f, k3 = 1.0f, k4 = 1.0f;
    float k5 = 1.0f, k6 = 1.0f, k7 = 1.0f, k8 = 1.0f;
    float inL = 1.0f;         // K[i][8t] for step 0 (neighbor k8 == 1)
    float inD = 1.0f;
    float c1a = 1.0f, c2a = 1.0f, c1b = 1.0f, c2b = 1.0f;
    float c1c = 1.0f, c2c = 1.0f, c1d = 1.0f, c2d = 1.0f;

    #pragma unroll 2
    for (int s = 0; s < 69; s++) {
        unsigned r = (unsigned)(s - t);                    // i-1
        if (r < 62u) {
            if (!(r & 1u)) {                               // new row-pair coeffs
                float q;
                q = cur.x * cur.x * (1.0f / 12.0f);
                c1a = 1.0f + 0.5f * cur.x + q;  c2a = 1.0f - q;
                q = cur.y * cur.y * (1.0f / 12.0f);
                c1b = 1.0f + 0.5f * cur.y + q;  c2b = 1.0f - q;
                q = cur.z * cur.z * (1.0f / 12.0f);
                c1c = 1.0f + 0.5f * cur.z + q;  c2c = 1.0f - q;
                q = cur.w * cur.w * (1.0f / 12.0f);
                c1d = 1.0f + 0.5f * cur.w + q;  c2d = 1.0f - q;
                cur = nxt; nxt = nx2;
                if (remaining > 0) {                        // stay in-bounds
                    nx2 = *ap; ap += 8; remaining--;
                }
            }
            // parallel b_j (independent of the serial chain)
            float b1 = fmaf(c1a, k1, -c2a * inD);
            float b2 = fmaf(c1a, k2, -c2a * k1);
            float b3 = fmaf(c1b, k3, -c2b * k2);
            float b4 = fmaf(c1b, k4, -c2b * k3);
            float b5 = fmaf(c1c, k5, -c2c * k4);
            float b6 = fmaf(c1c, k6, -c2c * k5);
            float b7 = fmaf(c1d, k7, -c2d * k6);
            float b8 = fmaf(c1d, k8, -c2d * k7);
            // serial chain: 8 single FFMAs
            k1 = fmaf(c1a, inL, b1);
            k2 = fmaf(c1a, k1,  b2);
            k3 = fmaf(c1b, k2,  b3);
            k4 = fmaf(c1b, k3,  b4);
            k5 = fmaf(c1c, k4,  b5);
            k6 = fmaf(c1c, k5,  b6);
            k7 = fmaf(c1d, k6,  b7);
            k8 = fmaf(c1d, k7,  b8);
        }
        inD = inL;
        // shuffle for the NEXT step, issued as soon as k8 is ready
        inL = __shfl_up_sync(0xffffffffu, k8, 1, 8);       // K[i+1][8t] from t-1
        if (t == 0) inL = 1.0f;                            // left boundary
    }

    // thread t=7 owns cols 57..64 -> k6 = K[62][62]
    if (t == 7)
        sh_res[warp][grp] = wgt * k6;
    __syncthreads();

    // ======== publish block partial + last-block fixed-order reduction ========
    if (threadIdx.x == 0) {
        float bsum = 0.0f;
        #pragma unroll
        for (int ww = 0; ww < WARPS_PER_BLOCK; ww++)
            bsum += (sh_res[ww][0] + sh_res[ww][1]) + (sh_res[ww][2] + sh_res[ww][3]);
        g_block[blockIdx.x] = bsum;
        __threadfence();
        unsigned tt = atomicAdd(&g_done, 1u);
        sh_last = (tt == NBLOCKS - 1);
    }
    __syncthreads();

    if (sh_last) {
        float s = 0.0f;
        #pragma unroll 1
        for (int i = threadIdx.x; i < NBLOCKS; i += THREADS_PER_BLOCK)
            s += g_block[i];
        sh_red[threadIdx.x] = s;
        __syncthreads();
        #pragma unroll
        for (int off = THREADS_PER_BLOCK / 2; off > 0; off >>= 1) {
            if (threadIdx.x < off) sh_red[threadIdx.x] += sh_red[threadIdx.x + off];
            __syncthreads();
        }
        if (threadIdx.x == 0) {
            out[0] = sh_red[0] * (1.0f / 4096.0f);
            g_done = 0;   // reset for next graph replay
        }
    }
}

extern "C" void kernel_launch(void* const* d_in, const int* in_sizes, int n_in,
                              void* d_out, int out_size)
{
    // Expected order: x [64*32*5], y [64*32*5], sigma_param [4].
    // Pick sigma defensively by element count.
    const float* x = nullptr;
    const float* yy = nullptr;
    const float* sp = nullptr;
    for (int i = 0; i < n_in; i++) {
        if (in_sizes[i] == CH - 1) { sp = (const float*)d_in[i]; }
        else if (!x)               { x  = (const float*)d_in[i]; }
        else if (!yy)              { yy = (const float*)d_in[i]; }
    }

    sig_kernel<<<NBLOCKS, THREADS_PER_BLOCK>>>(x, yy, sp, (float*)d_out);
}